// round 2
// baseline (speedup 1.0000x reference)
#include <cuda_runtime.h>

// Problem constants
#define B   2
#define D   160
#define H   192
#define W   160
#define HW  (H * W)          // 30720
#define DHW (D * H * W)      // 4915200
#define NVOX (B * DHW)       // 9830400 per channel (incl batch)
#define CH  5
#define WIN 9
#define PAD 4
#define INV_N (1.0f / 729.0f)

// Scratch (device globals: allocation-free)
__device__ float g_bufA[CH * NVOX];   // after W-pass
__device__ float g_bufB[CH * NVOX];   // after H-pass
__device__ double g_acc[4];           // cc_sum, dx_sum, dy_sum, dz_sum

// Warp-shuffle sum then one atomicAdd(double) per warp. Size-agnostic.
__device__ __forceinline__ void warp_reduce_atomic(float v, double* dst) {
#pragma unroll
    for (int off = 16; off > 0; off >>= 1)
        v += __shfl_down_sync(0xFFFFFFFFu, v, off);
    if ((threadIdx.x & 31) == 0) atomicAdd(dst, (double)v);
}

// ---------------------------------------------------------------------------
__global__ void k_zero() {
    if (threadIdx.x < 4) g_acc[threadIdx.x] = 0.0;
}

// ---------------------------------------------------------------------------
// Pass 1: 5 products + 9-tap box sum along W. One block per row (b,d,h).
__global__ void k_pass1(const float* __restrict__ F, const float* __restrict__ M) {
    __shared__ float s[CH][W + 2 * PAD];
    const int w = threadIdx.x;
    const int row = blockIdx.x;              // over B*D*H = 61440
    const int base = row * W;

    const float f = F[base + w];
    const float m = M[base + w];

    if (w < PAD) {
#pragma unroll
        for (int c = 0; c < CH; c++) s[c][w] = 0.f;
    }
    if (w >= W - PAD) {
#pragma unroll
        for (int c = 0; c < CH; c++) s[c][w + 2 * PAD] = 0.f;
    }
    s[0][w + PAD] = f;
    s[1][w + PAD] = m;
    s[2][w + PAD] = f * f;
    s[3][w + PAD] = m * m;
    s[4][w + PAD] = f * m;
    __syncthreads();

#pragma unroll
    for (int c = 0; c < CH; c++) {
        float sum = 0.f;
#pragma unroll
        for (int k = 0; k < WIN; k++) sum += s[c][w + k];
        g_bufA[c * NVOX + base + w] = sum;
    }
}

// ---------------------------------------------------------------------------
// Pass 2: 9-tap box sum along H, running window. One block per (ch,b,d) plane.
__global__ void k_pass2() {
    const int w = threadIdx.x;
    const int p = blockIdx.x;                // over CH*B*D = 1600
    const int c = p / (B * D);
    const int bd = p - c * (B * D);
    const float* __restrict__ in = g_bufA + (size_t)c * NVOX + (size_t)bd * HW;
    float* __restrict__ out = g_bufB + (size_t)c * NVOX + (size_t)bd * HW;

    float sum = 0.f;
#pragma unroll
    for (int h = 0; h <= PAD; h++) sum += in[h * W + w];

    for (int h = 0; h < H; h++) {
        out[h * W + w] = sum;
        const int hp = h + PAD + 1;
        const int hm = h - PAD;
        if (hp < H) sum += in[hp * W + w];
        if (hm >= 0) sum -= in[hm * W + w];
    }
}

// ---------------------------------------------------------------------------
// Pass 3: box sum along D + per-voxel CC + global reduction.
#define SEG  4
#define DSEG (D / SEG)

__global__ void k_pass3_cc() {
    const int w = threadIdx.x;
    int blk = blockIdx.x;                    // over B*H*SEG = 1536
    const int seg = blk % SEG; blk /= SEG;
    const int h = blk % H;
    const int b = blk / H;
    const int d0 = seg * DSEG;

    const size_t colbase = (size_t)b * DHW + (size_t)h * W + w;

    float s[CH];
#pragma unroll
    for (int c = 0; c < CH; c++) {
        float acc = 0.f;
        for (int d = d0 - PAD; d <= d0 + PAD; d++) {
            if (d >= 0 && d < D)
                acc += g_bufB[(size_t)c * NVOX + colbase + (size_t)d * HW];
        }
        s[c] = acc;
    }

    float local = 0.f;
    for (int d = d0; d < d0 + DSEG; d++) {
        const float mf  = s[0] * INV_N;
        const float mm  = s[1] * INV_N;
        const float vF  = s[2] - mf * mf;
        const float vM  = s[3] - mm * mm;
        const float cov = s[4] - mf * mm;
        local += (cov * cov) / (vF * vM + 1e-8f);

        const int dp = d + PAD + 1;
        const int dm = d - PAD;
#pragma unroll
        for (int c = 0; c < CH; c++) {
            float add = 0.f, sub = 0.f;
            if (dp < D)  add = g_bufB[(size_t)c * NVOX + colbase + (size_t)dp * HW];
            if (dm >= 0) sub = g_bufB[(size_t)c * NVOX + colbase + (size_t)dm * HW];
            s[c] += add - sub;
        }
    }

    warp_reduce_atomic(local, &g_acc[0]);
}

// ---------------------------------------------------------------------------
// Flow gradient loss: |forward diff| along D (dy), H (dx), W (dz).
#define NF (B * 3 * DHW)   // 29491200

__global__ void k_grad(const float* __restrict__ flow) {
    float sdx = 0.f, sdy = 0.f, sdz = 0.f;
    const int stride = gridDim.x * blockDim.x;
    for (int i = blockIdx.x * blockDim.x + threadIdx.x; i < NF; i += stride) {
        const float v = flow[i];
        const int w = i % W;
        int t = i / W;
        const int h = t % H;
        t /= H;
        const int d = t % D;
        if (w < W - 1) sdz += fabsf(flow[i + 1] - v);
        if (h < H - 1) sdx += fabsf(flow[i + W] - v);
        if (d < D - 1) sdy += fabsf(flow[i + HW] - v);
    }

    warp_reduce_atomic(sdx, &g_acc[1]);
    warp_reduce_atomic(sdy, &g_acc[2]);
    warp_reduce_atomic(sdz, &g_acc[3]);
}

// ---------------------------------------------------------------------------
__global__ void k_finalize(float* __restrict__ out) {
    const double L_sim = -(g_acc[0] / (double)NVOX);
    const double ndx = (double)B * 3.0 * D * (H - 1) * W;
    const double ndy = (double)B * 3.0 * (D - 1) * H * W;
    const double ndz = (double)B * 3.0 * D * H * (W - 1);
    const double L_reg = g_acc[1] / ndx + g_acc[2] / ndy + g_acc[3] / ndz;
    out[0] = (float)(L_sim + L_reg);
    out[1] = (float)L_sim;
    out[2] = (float)L_reg;
}

// ---------------------------------------------------------------------------
extern "C" void kernel_launch(void* const* d_in, const int* in_sizes, int n_in,
                              void* d_out, int out_size) {
    const float* I_fixed = (const float*)d_in[0];
    const float* I_moved = (const float*)d_in[1];
    const float* flow    = (const float*)d_in[2];
    float* out = (float*)d_out;

    k_zero<<<1, 32>>>();
    k_pass1<<<B * D * H, W>>>(I_fixed, I_moved);
    k_pass2<<<CH * B * D, W>>>();
    k_pass3_cc<<<B * H * SEG, W>>>();
    k_grad<<<2048, 256>>>(flow);
    k_finalize<<<1, 1>>>(out);
}

// round 4
// speedup vs baseline: 1.6726x; 1.6726x over previous
#include <cuda_runtime.h>

// Problem constants
#define B   2
#define D   160
#define H   192
#define W   160
#define HW  (H * W)          // 30720
#define DHW (D * H * W)      // 4915200
#define NVOX (B * DHW)       // 9830400 per channel
#define CH  5
#define WIN 9
#define PAD 4
#define INV_N (1.0f / 729.0f)

// H segmentation for k_pass12
#define HSEG  64
#define NSEGH (H / HSEG)     // 3

// D segmentation for k_pass3
#define SEG  8
#define DSEG (D / SEG)       // 20

// Scratch
__device__ float g_bufB[CH * NVOX];   // W+H box-filtered products
__device__ double g_acc[4];           // cc_sum, dx_sum, dy_sum, dz_sum

__device__ __forceinline__ void warp_reduce_atomic(float v, double* dst) {
#pragma unroll
    for (int off = 16; off > 0; off >>= 1)
        v += __shfl_down_sync(0xFFFFFFFFu, v, off);
    if ((threadIdx.x & 31) == 0) atomicAdd(dst, (double)v);
}

__global__ void k_zero() {
    if (threadIdx.x < 4) g_acc[threadIdx.x] = 0.0;
}

// ---------------------------------------------------------------------------
// Fused pass 1+2: products -> 9-tap W box -> 9-tap H box (running window).
// Block = (b, d, h-segment); 160 threads = w. Ring of 9 W-box rows in smem.
__global__ void k_pass12(const float* __restrict__ F, const float* __restrict__ M) {
    __shared__ float sf[W + 2 * PAD];
    __shared__ float sm[W + 2 * PAD];
    __shared__ float ring[WIN][CH][W];          // 28.8 KB

    const int w = threadIdx.x;
    int blk = blockIdx.x;                        // over B*D*NSEGH = 960
    const int hs = blk % NSEGH; blk /= NSEGH;
    const int d  = blk % D;
    const int b  = blk / D;
    const int h0 = hs * HSEG;

    const size_t plane = (size_t)(b * D + d) * HW;
    const float* __restrict__ Fp = F + plane;
    const float* __restrict__ Mp = M + plane;

    if (w < PAD)     { sf[w] = 0.f;           sm[w] = 0.f; }
    if (w >= W - PAD){ sf[w + 2 * PAD] = 0.f; sm[w + 2 * PAD] = 0.f; }

    float s0 = 0.f, s1 = 0.f, s2 = 0.f, s3 = 0.f, s4 = 0.f;

    // W-box of row r for all 5 channels into n0..n4
#define WBOX(r, n0, n1, n2, n3, n4)                                         \
    {                                                                       \
        const bool valid = ((r) >= 0 && (r) < H);                           \
        const float fv_ = valid ? Fp[(r) * W + w] : 0.f;                    \
        const float mv_ = valid ? Mp[(r) * W + w] : 0.f;                    \
        __syncthreads();                                                    \
        sf[w + PAD] = fv_; sm[w + PAD] = mv_;                               \
        __syncthreads();                                                    \
        n0 = 0.f; n1 = 0.f; n2 = 0.f; n3 = 0.f; n4 = 0.f;                   \
        _Pragma("unroll")                                                   \
        for (int k = 0; k < WIN; k++) {                                     \
            const float fk = sf[w + k];                                     \
            const float mk = sm[w + k];                                     \
            n0 += fk; n1 += mk;                                             \
            n2 = fmaf(fk, fk, n2);                                          \
            n3 = fmaf(mk, mk, n3);                                          \
            n4 = fmaf(fk, mk, n4);                                          \
        }                                                                   \
    }

    // Prologue: ring <- rows h0-4 .. h0+4, s = their sum
    for (int r = h0 - PAD; r <= h0 + PAD; r++) {
        float n0, n1, n2, n3, n4;
        WBOX(r, n0, n1, n2, n3, n4);
        const int slot = (r + 9) % 9;
        ring[slot][0][w] = n0; ring[slot][1][w] = n1; ring[slot][2][w] = n2;
        ring[slot][3][w] = n3; ring[slot][4][w] = n4;
        s0 += n0; s1 += n1; s2 += n2; s3 += n3; s4 += n4;
    }

    for (int h = h0; h < h0 + HSEG; h++) {
        // s holds H-window [h-4, h+4] of W-box rows
        const size_t o = plane + (size_t)h * W + w;
        g_bufB[0 * NVOX + o] = s0;
        g_bufB[1 * NVOX + o] = s1;
        g_bufB[2 * NVOX + o] = s2;
        g_bufB[3 * NVOX + o] = s3;
        g_bufB[4 * NVOX + o] = s4;

        if (h + 1 < h0 + HSEG) {
            const int r = h + 5;
            float n0, n1, n2, n3, n4;
            WBOX(r, n0, n1, n2, n3, n4);
            const int slot = (r + 9) % 9;
            s0 += n0 - ring[slot][0][w]; ring[slot][0][w] = n0;
            s1 += n1 - ring[slot][1][w]; ring[slot][1][w] = n1;
            s2 += n2 - ring[slot][2][w]; ring[slot][2][w] = n2;
            s3 += n3 - ring[slot][3][w]; ring[slot][3][w] = n3;
            s4 += n4 - ring[slot][4][w]; ring[slot][4][w] = n4;
        }
    }
#undef WBOX
}

// ---------------------------------------------------------------------------
// Pass 3: 9-tap D box (running window) + per-voxel CC + reduction.
__global__ void k_pass3_cc() {
    const int w = threadIdx.x;
    int blk = blockIdx.x;                    // over B*H*SEG = 3072
    const int seg = blk % SEG; blk /= SEG;
    const int h = blk % H;
    const int b = blk / H;
    const int d0 = seg * DSEG;

    const size_t colbase = (size_t)b * DHW + (size_t)h * W + w;

    float s[CH];
#pragma unroll
    for (int c = 0; c < CH; c++) {
        float acc = 0.f;
        for (int d = d0 - PAD; d <= d0 + PAD; d++) {
            if (d >= 0 && d < D)
                acc += g_bufB[(size_t)c * NVOX + colbase + (size_t)d * HW];
        }
        s[c] = acc;
    }

    float local = 0.f;
    for (int d = d0; d < d0 + DSEG; d++) {
        const float mf  = s[0] * INV_N;
        const float mm  = s[1] * INV_N;
        const float vF  = s[2] - mf * mf;
        const float vM  = s[3] - mm * mm;
        const float cov = s[4] - mf * mm;
        local += (cov * cov) / (vF * vM + 1e-8f);

        const int dp = d + PAD + 1;
        const int dm = d - PAD;
#pragma unroll
        for (int c = 0; c < CH; c++) {
            float add = 0.f, sub = 0.f;
            if (dp < D)  add = g_bufB[(size_t)c * NVOX + colbase + (size_t)dp * HW];
            if (dm >= 0) sub = g_bufB[(size_t)c * NVOX + colbase + (size_t)dm * HW];
            s[c] += add - sub;
        }
    }

    warp_reduce_atomic(local, &g_acc[0]);
}

// ---------------------------------------------------------------------------
// Flow gradient: block per (b,c,d) plane, walk h.
// dx = h-diff, dy = d-diff (NEXT PLANE = base + HW), dz = w-diff.
__global__ void k_grad(const float* __restrict__ flow) {
    __shared__ float row[W];
    const int w = threadIdx.x;
    const int blk = blockIdx.x;              // (b*3 + c)*D + d, 960 blocks
    const int d = blk % D;
    const size_t base = (size_t)blk * HW;
    const bool hasD = (d < D - 1);

    float sdx = 0.f, sdy = 0.f, sdz = 0.f;
    float prev = 0.f;

    for (int h = 0; h < H; h++) {
        const float cur = flow[base + (size_t)h * W + w];
        row[w] = cur;
        __syncthreads();
        if (w < W - 1) sdz += fabsf(row[w + 1] - cur);
        if (hasD)      sdy += fabsf(flow[base + (size_t)HW + (size_t)h * W + w] - cur);
        if (h > 0)     sdx += fabsf(cur - prev);
        prev = cur;
        __syncthreads();
    }

    warp_reduce_atomic(sdx, &g_acc[1]);
    warp_reduce_atomic(sdy, &g_acc[2]);
    warp_reduce_atomic(sdz, &g_acc[3]);
}

// ---------------------------------------------------------------------------
__global__ void k_finalize(float* __restrict__ out) {
    const double L_sim = -(g_acc[0] / (double)NVOX);
    const double ndx = (double)B * 3.0 * D * (H - 1) * W;
    const double ndy = (double)B * 3.0 * (D - 1) * H * W;
    const double ndz = (double)B * 3.0 * D * H * (W - 1);
    const double L_reg = g_acc[1] / ndx + g_acc[2] / ndy + g_acc[3] / ndz;
    out[0] = (float)(L_sim + L_reg);
    out[1] = (float)L_sim;
    out[2] = (float)L_reg;
}

// ---------------------------------------------------------------------------
extern "C" void kernel_launch(void* const* d_in, const int* in_sizes, int n_in,
                              void* d_out, int out_size) {
    const float* I_fixed = (const float*)d_in[0];
    const float* I_moved = (const float*)d_in[1];
    const float* flow    = (const float*)d_in[2];
    float* out = (float*)d_out;

    k_zero<<<1, 32>>>();
    k_pass12<<<B * D * NSEGH, W>>>(I_fixed, I_moved);
    k_pass3_cc<<<B * H * SEG, W>>>();
    k_grad<<<B * 3 * D, W>>>(flow);
    k_finalize<<<1, 1>>>(out);
}